// round 6
// baseline (speedup 1.0000x reference)
#include <cuda_runtime.h>
#include <cstdint>

// Screen tiling constants (match reference)
#define SW 1280
#define SH 720
#define TL 16
#define NBW 80           // ceil(1280/16)
#define NBH 45           // ceil(720/16)
#define NUM_BLOCK (NBW*NBH)   // 3600
#define N_POINTS 32768

// Precomputed separable masks (bytes 0/1). Static device scratch (no allocs).
__device__ unsigned char g_maskX[NBW * N_POINTS];   // 2.62 MB
__device__ unsigned char g_maskY[NBH * N_POINTS];   // 1.47 MB

// ---------------------------------------------------------------------------
// Phase 1: per point, compute clamped AABB -> tile index ranges, then write
// one byte per (tile-row/col, point). Writes are fully coalesced across
// threads (adjacent n -> adjacent bytes) for each of the 80+45 rows.
// ---------------------------------------------------------------------------
__global__ void build_masks_kernel(const float* __restrict__ pos2d,
                                   const float* __restrict__ radius)
{
    int n = blockIdx.x * blockDim.x + threadIdx.x;
    if (n >= N_POINTS) return;

    float px = pos2d[2 * n + 0];
    float py = pos2d[2 * n + 1];
    float r  = radius[n];

    // Match reference exactly: clip to [0, W]/[0, H] then truncate to int32.
    int xmin = (int)fminf(fmaxf(px - r, 0.0f), (float)SW);
    int xmax = (int)fminf(fmaxf(px + r, 0.0f), (float)SW);
    int ymin = (int)fminf(fmaxf(py - r, 0.0f), (float)SH);
    int ymax = (int)fminf(fmaxf(py + r, 0.0f), (float)SH);

    // Tile edges are exact multiples of 16 (no screen-edge clamping needed):
    //   in_mask <=> xi in [xmin>>4, (xmax+15)>>4)   when xmax > xmin
    int x0 = xmin >> 4;
    int x1 = (xmax + 15) >> 4;
    if (xmax <= xmin) x1 = x0;          // degenerate AABB -> empty
    int y0 = ymin >> 4;
    int y1 = (ymax + 15) >> 4;
    if (ymax <= ymin) y1 = y0;

    #pragma unroll
    for (int xi = 0; xi < NBW; xi++)
        g_maskX[xi * N_POINTS + n] = (unsigned char)((xi >= x0) & (xi < x1));

    #pragma unroll
    for (int yi = 0; yi < NBH; yi++)
        g_maskY[yi * N_POINTS + n] = (unsigned char)((yi >= y0) & (yi < y1));
}

// ---------------------------------------------------------------------------
// Phase 2: out[t*N + n] = float(maskX[t/45][n] & maskY[t%45][n]).
// OUTPUT IS FLOAT32 (harness materializes the bool mask as f32; rel_err==1.0
// with byte writes proved it). Each thread: 2x 4-byte mask loads (L2 hits),
// AND, unpack 4 bytes -> 0.0f/1.0f, one float4 streaming store (.cs so the
// 472 MB write stream does not evict the 4 MB of hot masks from L2).
// grid = (32768/(256*4)=32, 3600), block = 256.
// ---------------------------------------------------------------------------
__global__ void __launch_bounds__(256, 8)
expand_kernel(float* __restrict__ out)
{
    int t = blockIdx.y;                       // tile id, 0..3599
    int n4 = (blockIdx.x * blockDim.x + threadIdx.x) * 4;

    int xi = t / NBH;
    int yi = t - xi * NBH;

    unsigned int a = __ldg(reinterpret_cast<const unsigned int*>(&g_maskX[xi * N_POINTS + n4]));
    unsigned int b = __ldg(reinterpret_cast<const unsigned int*>(&g_maskY[yi * N_POINTS + n4]));
    unsigned int m = a & b;                   // bytes are 0x00 or 0x01

    float4 o;
    o.x = (float)( m        & 1u);
    o.y = (float)((m >>  8) & 1u);
    o.z = (float)((m >> 16) & 1u);
    o.w = (float)((m >> 24) & 1u);

    __stcs(reinterpret_cast<float4*>(out + (size_t)t * N_POINTS + n4), o);
}

extern "C" void kernel_launch(void* const* d_in, const int* in_sizes, int n_in,
                              void* d_out, int out_size)
{
    const float* pos2d  = (const float*)d_in[0];
    const float* radius = (const float*)d_in[1];
    float* out          = (float*)d_out;

    build_masks_kernel<<<(N_POINTS + 255) / 256, 256>>>(pos2d, radius);

    dim3 grid(N_POINTS / (256 * 4), NUM_BLOCK);   // (32, 3600)
    expand_kernel<<<grid, 256>>>(out);
}